// round 4
// baseline (speedup 1.0000x reference)
#include <cuda_runtime.h>
#include <cstdint>

// QSVT <Z> closed form, fully fused (single kernel node):
//   x = clamp(x,-1,1), u = x^2, s = sqrt(1-u)
//   <Z>(x) = cos(x)*h(u) + s*x*sin(x)*g(u),  deg_u h <= 7, deg_u g <= 6.
// (phi[7] and theta are diagonal phases -> dead for <Z>.)
//
// Per-block setup (threads 0..15, hidden under the block's initial LDG
// latency): fp32 Bloch recurrence at the 8 Chebyshev-Gauss nodes in
// y = 2u-1 (node/DCT cosines from a compile-time table), fp32 8-pt DCT ->
// Chebyshev coeffs, then the Cheb->monomial transform in DOUBLE (its integer
// T-matrix has entries up to 112 -> x100 error amplification if done in
// fp32). Main math: packed-f32x2 Horner in y.

typedef unsigned long long u64;

// cos(m*pi/16), m = 0..16
__device__ __constant__ float c_cos16f[17] = {
    1.0f,
    0.980785280403230449f,  0.923879532511286756f,
    0.831469612302545237f,  0.707106781186547524f,
    0.555570233019602225f,  0.382683432365089772f,
    0.195090322016128268f,  0.0f,
   -0.195090322016128268f, -0.382683432365089772f,
   -0.555570233019602225f, -0.707106781186547524f,
   -0.831469612302545237f, -0.923879532511286756f,
   -0.980785280403230449f, -1.0f
};

// T_k(y) monomial coefficients, k=0..7 (integers, exact)
__device__ __constant__ double c_Td[8][8] = {
    { 1,  0,  0,  0,   0,    0,  0,  0},
    { 0,  1,  0,  0,   0,    0,  0,  0},
    {-1,  0,  2,  0,   0,    0,  0,  0},
    { 0, -3,  0,  4,   0,    0,  0,  0},
    { 1,  0, -8,  0,   8,    0,  0,  0},
    { 0,  5,  0,-20,   0,   16,  0,  0},
    {-1,  0, 18,  0, -48,    0, 32,  0},
    { 0, -7,  0, 56,   0, -112,  0, 64}
};

__device__ __forceinline__ float cos16f(int m) {
    m &= 31;
    if (m > 16) m = 32 - m;
    return c_cos16f[m];
}

// ---------------------- packed f32x2 helpers ----------------------
__device__ __forceinline__ u64 pk2(float lo, float hi) {
    u64 r; asm("mov.b64 %0, {%1, %2};" : "=l"(r) : "f"(lo), "f"(hi)); return r;
}
__device__ __forceinline__ void unpk2(u64 v, float& lo, float& hi) {
    asm("mov.b64 {%0, %1}, %2;" : "=f"(lo), "=f"(hi) : "l"(v));
}
__device__ __forceinline__ u64 fma2(u64 a, u64 b, u64 c) {
    u64 d; asm("fma.rn.f32x2 %0, %1, %2, %3;" : "=l"(d) : "l"(a), "l"(b), "l"(c)); return d;
}
__device__ __forceinline__ u64 mul2(u64 a, u64 b) {
    u64 d; asm("mul.rn.f32x2 %0, %1, %2;" : "=l"(d) : "l"(a), "l"(b)); return d;
}
// ---------------------- scalar MUFU ----------------------
__device__ __forceinline__ float aprx_sqrt(float x) {
    float r; asm("sqrt.approx.f32 %0, %1;" : "=f"(r) : "f"(x)); return r;
}
__device__ __forceinline__ float aprx_sin(float x) {
    float r; asm("sin.approx.f32 %0, %1;" : "=f"(r) : "f"(x)); return r;
}
__device__ __forceinline__ float aprx_cos(float x) {
    float r; asm("cos.approx.f32 %0, %1;" : "=f"(r) : "f"(x)); return r;
}

// Two elements packed; returns packed <Z>.
__device__ __forceinline__ u64 qsvt_pair(float xa, float xb,
                                         const u64* __restrict__ K,
                                         u64 TWO, u64 NEG1) {
    xa = fminf(fmaxf(xa, -1.0f), 1.0f);
    xb = fminf(fmaxf(xb, -1.0f), 1.0f);
    float ta = fmaxf(fmaf(-xa, xa, 1.0f), 0.0f);
    float tb = fmaxf(fmaf(-xb, xb, 1.0f), 0.0f);
    float sa = aprx_sqrt(ta), sb = aprx_sqrt(tb);
    float sina = aprx_sin(xa), cosa = aprx_cos(xa);
    float sinb = aprx_sin(xb), cosb = aprx_cos(xb);

    u64 X = pk2(xa, xb);
    u64 U = mul2(X, X);
    u64 Y = fma2(U, TWO, NEG1);                            // y = 2u-1
    u64 M1 = mul2(mul2(X, pk2(sa, sb)), pk2(sina, sinb));  // s*x*sin(x)
    u64 CS = pk2(cosa, cosb);

    // Horner in y: h (deg 7), coeffs K[0..7]
    u64 H = K[7];
    H = fma2(H, Y, K[6]);
    H = fma2(H, Y, K[5]);
    H = fma2(H, Y, K[4]);
    H = fma2(H, Y, K[3]);
    H = fma2(H, Y, K[2]);
    H = fma2(H, Y, K[1]);
    H = fma2(H, Y, K[0]);

    // Horner in y: g (deg 6), coeffs K[8..14]
    u64 G = K[14];
    G = fma2(G, Y, K[13]);
    G = fma2(G, Y, K[12]);
    G = fma2(G, Y, K[11]);
    G = fma2(G, Y, K[10]);
    G = fma2(G, Y, K[9]);
    G = fma2(G, Y, K[8]);

    return fma2(M1, G, mul2(CS, H));   // cos*h + s*x*sin*g
}

__global__ void __launch_bounds__(256) qsvt_fused(const float* __restrict__ xin,
                                                  const float* __restrict__ phi,
                                                  float* __restrict__ out,
                                                  int n) {
    __shared__ float s_node[16];   // [0..7] h node values, [8..15] g node values
    __shared__ float s_cheb[16];   // Chebyshev coeffs (same layout)
    __shared__ u64   s_K[16];      // dup-packed monomial coeffs

    long long tid  = (long long)blockIdx.x * blockDim.x + threadIdx.x;
    long long base = tid * 8;
    bool full = (base + 8 <= (long long)n);

    // Issue this thread's global loads FIRST so the per-block coefficient
    // chain below hides under the DRAM latency.
    float4 a, b;
    if (full) {
        a = *reinterpret_cast<const float4*>(xin + base);
        b = *reinterpret_cast<const float4*>(xin + base + 4);
    }

    int t = threadIdx.x;
    if (t < 16) {
        // rotation constants from fp32 trig (error ~1e-7, benign)
        float C[7], SP[7], SN[7];
#pragma unroll
        for (int k = 0; k < 7; k++) {
            float ss, cc;
            sincosf(2.0f * __ldg(phi + k), &ss, &cc);
            float sg = (k & 1) ? -1.0f : 1.0f;
            C[k] = cc; SP[k] = sg * ss; SN[k] = -sg * ss;
        }
        // fp32 Bloch recurrence at node j, for state family m (0->h, 1->g)
        int j = t & 7, m = t >> 3;
        float y = cos16f(2 * j + 1);
        float u = 0.5f * (y + 1.0f);
        float x = sqrtf(u);
        float s = sqrtf(1.0f - u);
        float A = 1.0f - 2.0f * u;
        float B = 2.0f * s * x;
        float rx, w, rz;
        if (m == 0) { rx = 0.0f; w = 0.0f; rz = 1.0f; }
        else        { rx = C[0]; w = SN[0]; rz = 0.0f; }
#pragma unroll
        for (int jj = 1; jj <= 7; jj++) {
            float nrx = A * rx + B * rz;
            float nrz = B * rx - A * rz;
            rx = nrx; rz = nrz;
            if (jj < 7) {
                float rx2 = C[jj] * rx + SP[jj] * w;
                w  = C[jj] * w + SN[jj] * rx;
                rx = rx2;
            }
        }
        s_node[t] = (m == 0) ? rz : rz / (s * x);
        __syncwarp(0x0000ffffu);

        // fp32 8-pt DCT: coeff k of family m
        int k = t & 7;
        int fam = (t & 8);    // 0 or 8
        float acc = 0.0f;
#pragma unroll
        for (int j2 = 0; j2 < 8; j2++)
            acc += s_node[fam + j2] * cos16f(k * (2 * j2 + 1));
        acc *= ((k == 0) ? 1.0f : 2.0f) * 0.125f;
        s_cheb[t] = acc;
        __syncwarp(0x0000ffffu);

        // Cheb -> monomial-in-y, in double (T entries up to 112)
        double md = 0.0;
#pragma unroll
        for (int k2 = 0; k2 < 8; k2++)
            md += (double)s_cheb[fam + k2] * c_Td[k2][j];
        float f = (float)md;
        s_K[t] = ((u64)__float_as_uint(f) << 32) | (u64)__float_as_uint(f);
    }
    __syncthreads();

    if (base >= (long long)n) return;

    u64 K[16];
#pragma unroll
    for (int i = 0; i < 16; i++) K[i] = s_K[i];

    const u64 TWO  = pk2(2.0f, 2.0f);
    const u64 NEG1 = pk2(-1.0f, -1.0f);

    if (full) {
        u64 r01 = qsvt_pair(a.x, a.y, K, TWO, NEG1);
        u64 r23 = qsvt_pair(a.z, a.w, K, TWO, NEG1);
        u64 r45 = qsvt_pair(b.x, b.y, K, TWO, NEG1);
        u64 r67 = qsvt_pair(b.z, b.w, K, TWO, NEG1);

        float4 o1, o2;
        unpk2(r01, o1.x, o1.y);
        unpk2(r23, o1.z, o1.w);
        unpk2(r45, o2.x, o2.y);
        unpk2(r67, o2.z, o2.w);
        *reinterpret_cast<float4*>(out + base)     = o1;
        *reinterpret_cast<float4*>(out + base + 4) = o2;
    } else {
        for (long long i = base; i < n; i++) {
            u64 r = qsvt_pair(xin[i], 0.0f, K, TWO, NEG1);
            float lo, hi;
            unpk2(r, lo, hi);
            out[i] = lo;
        }
    }
}

extern "C" void kernel_launch(void* const* d_in, const int* in_sizes, int n_in,
                              void* d_out, int out_size) {
    const float* x   = (const float*)d_in[0];
    // d_in[1] = theta: dead (diagonal phase, does not affect <Z>)
    const float* phi = (const float*)d_in[2];
    float* out = (float*)d_out;

    int n = out_size;
    long long threads = ((long long)n + 7) / 8;
    int blocks = (int)((threads + 255) / 256);
    qsvt_fused<<<blocks, 256>>>(x, phi, out, n);
}

// round 5
// speedup vs baseline: 1.4779x; 1.4779x over previous
#include <cuda_runtime.h>
#include <cstdint>

// QSVT <Z> closed form:
//   x = clamp(x,-1,1), u = x^2, s = sqrt(1-u)
//   <Z>(x) = cos(x)*h(u) + s*x*sin(x)*g(u),  deg_u h <= 7, deg_u g <= 6.
// (phi[7] and theta are diagonal phases -> dead for <Z>.)
//
// Two kernels:
//  - qsvt_setup (1 warp, ~2us): fp32 Bloch recurrence at the 8 Chebyshev-
//    Gauss nodes in y = 2u-1 (cosines from a compile-time table), fp32 8-pt
//    DCT -> Chebyshev coeffs, Cheb->monomial-in-y transform in DOUBLE only
//    (integer T-matrix entries up to 112 -> x100 amplification in fp32).
//    NO fp64 sqrt/div/trig (those cost ~10us in an earlier round).
//  - qsvt_main (proven 24us): packed-f32x2 Horner in y, 8 elems/thread.

typedef unsigned long long u64;

__device__ u64 g_pk[16];  // [0..7] h monomial coeffs (dup-packed), [8..14] g

// cos(m*pi/16), m = 0..16
__device__ __constant__ float c_cos16f[17] = {
    1.0f,
    0.980785280403230449f,  0.923879532511286756f,
    0.831469612302545237f,  0.707106781186547524f,
    0.555570233019602225f,  0.382683432365089772f,
    0.195090322016128268f,  0.0f,
   -0.195090322016128268f, -0.382683432365089772f,
   -0.555570233019602225f, -0.707106781186547524f,
   -0.831469612302545237f, -0.923879532511286756f,
   -0.980785280403230449f, -1.0f
};

// T_k(y) monomial coefficients, k=0..7 (integers, exact)
__device__ __constant__ double c_Td[8][8] = {
    { 1,  0,  0,  0,   0,    0,  0,  0},
    { 0,  1,  0,  0,   0,    0,  0,  0},
    {-1,  0,  2,  0,   0,    0,  0,  0},
    { 0, -3,  0,  4,   0,    0,  0,  0},
    { 1,  0, -8,  0,   8,    0,  0,  0},
    { 0,  5,  0,-20,   0,   16,  0,  0},
    {-1,  0, 18,  0, -48,    0, 32,  0},
    { 0, -7,  0, 56,   0, -112,  0, 64}
};

__device__ __forceinline__ float cos16f(int m) {
    m &= 31;
    if (m > 16) m = 32 - m;
    return c_cos16f[m];
}

// ------------------- setup: one warp, fp32 (+8 DFMAs) -------------------
__global__ void qsvt_setup(const float* __restrict__ phi) {
    __shared__ float s_node[16];
    __shared__ float s_cheb[16];
    int t = threadIdx.x;
    if (t >= 16) return;

    float C[7], SP[7], SN[7];
#pragma unroll
    for (int k = 0; k < 7; k++) {
        float ss, cc;
        sincosf(2.0f * __ldg(phi + k), &ss, &cc);
        float sg = (k & 1) ? -1.0f : 1.0f;
        C[k] = cc; SP[k] = sg * ss; SN[k] = -sg * ss;
    }

    int j = t & 7, m = t >> 3;
    float y = cos16f(2 * j + 1);
    float u = 0.5f * (y + 1.0f);
    float x = sqrtf(u);
    float s = sqrtf(1.0f - u);
    float A = 1.0f - 2.0f * u;
    float B = 2.0f * s * x;
    float rx, w, rz;
    if (m == 0) { rx = 0.0f; w = 0.0f; rz = 1.0f; }   // -> h
    else        { rx = C[0]; w = SN[0]; rz = 0.0f; }  // -> s*x*g
#pragma unroll
    for (int jj = 1; jj <= 7; jj++) {
        float nrx = A * rx + B * rz;
        float nrz = B * rx - A * rz;
        rx = nrx; rz = nrz;
        if (jj < 7) {
            float rx2 = C[jj] * rx + SP[jj] * w;
            w  = C[jj] * w + SN[jj] * rx;
            rx = rx2;
        }
    }
    s_node[t] = (m == 0) ? rz : rz / (s * x);
    __syncwarp(0x0000ffffu);

    // fp32 8-pt DCT
    int fam = (t & 8);
    float acc = 0.0f;
#pragma unroll
    for (int j2 = 0; j2 < 8; j2++)
        acc += s_node[fam + j2] * cos16f(j * (2 * j2 + 1));
    acc *= ((j == 0) ? 1.0f : 2.0f) * 0.125f;
    s_cheb[t] = acc;
    __syncwarp(0x0000ffffu);

    // Cheb -> monomial-in-y (double; cheap 8-term dot)
    double md = 0.0;
#pragma unroll
    for (int k2 = 0; k2 < 8; k2++)
        md += (double)s_cheb[fam + k2] * c_Td[k2][j];
    float f = (float)md;
    u64 pkv = ((u64)__float_as_uint(f) << 32) | (u64)__float_as_uint(f);
    if (m == 0) g_pk[j] = pkv;
    else if (j < 7) g_pk[8 + j] = pkv;   // g has deg 6
    if (t == 15) g_pk[15] = 0ULL;
}

// ---------------------- packed f32x2 helpers ----------------------
__device__ __forceinline__ u64 pk2(float lo, float hi) {
    u64 r; asm("mov.b64 %0, {%1, %2};" : "=l"(r) : "f"(lo), "f"(hi)); return r;
}
__device__ __forceinline__ void unpk2(u64 v, float& lo, float& hi) {
    asm("mov.b64 {%0, %1}, %2;" : "=f"(lo), "=f"(hi) : "l"(v));
}
__device__ __forceinline__ u64 fma2(u64 a, u64 b, u64 c) {
    u64 d; asm("fma.rn.f32x2 %0, %1, %2, %3;" : "=l"(d) : "l"(a), "l"(b), "l"(c)); return d;
}
__device__ __forceinline__ u64 mul2(u64 a, u64 b) {
    u64 d; asm("mul.rn.f32x2 %0, %1, %2;" : "=l"(d) : "l"(a), "l"(b)); return d;
}
// ---------------------- scalar MUFU ----------------------
__device__ __forceinline__ float aprx_sqrt(float x) {
    float r; asm("sqrt.approx.f32 %0, %1;" : "=f"(r) : "f"(x)); return r;
}
__device__ __forceinline__ float aprx_sin(float x) {
    float r; asm("sin.approx.f32 %0, %1;" : "=f"(r) : "f"(x)); return r;
}
__device__ __forceinline__ float aprx_cos(float x) {
    float r; asm("cos.approx.f32 %0, %1;" : "=f"(r) : "f"(x)); return r;
}

// Two elements packed; returns packed <Z>.
__device__ __forceinline__ u64 qsvt_pair(float xa, float xb,
                                         const u64* __restrict__ K,
                                         u64 TWO, u64 NEG1) {
    xa = fminf(fmaxf(xa, -1.0f), 1.0f);
    xb = fminf(fmaxf(xb, -1.0f), 1.0f);
    float ta = fmaxf(fmaf(-xa, xa, 1.0f), 0.0f);
    float tb = fmaxf(fmaf(-xb, xb, 1.0f), 0.0f);
    float sa = aprx_sqrt(ta), sb = aprx_sqrt(tb);
    float sina = aprx_sin(xa), cosa = aprx_cos(xa);
    float sinb = aprx_sin(xb), cosb = aprx_cos(xb);

    u64 X = pk2(xa, xb);
    u64 U = mul2(X, X);
    u64 Y = fma2(U, TWO, NEG1);                            // y = 2u-1
    u64 M1 = mul2(mul2(X, pk2(sa, sb)), pk2(sina, sinb));  // s*x*sin(x)
    u64 CS = pk2(cosa, cosb);

    // Horner in y: h (deg 7), coeffs K[0..7]
    u64 H = K[7];
    H = fma2(H, Y, K[6]);
    H = fma2(H, Y, K[5]);
    H = fma2(H, Y, K[4]);
    H = fma2(H, Y, K[3]);
    H = fma2(H, Y, K[2]);
    H = fma2(H, Y, K[1]);
    H = fma2(H, Y, K[0]);

    // Horner in y: g (deg 6), coeffs K[8..14]
    u64 G = K[14];
    G = fma2(G, Y, K[13]);
    G = fma2(G, Y, K[12]);
    G = fma2(G, Y, K[11]);
    G = fma2(G, Y, K[10]);
    G = fma2(G, Y, K[9]);
    G = fma2(G, Y, K[8]);

    return fma2(M1, G, mul2(CS, H));   // cos*h + s*x*sin*g
}

__global__ void __launch_bounds__(256) qsvt_main(const float* __restrict__ xin,
                                                 float* __restrict__ out,
                                                 int n) {
    u64 K[16];
    {
        const ulonglong2* p = reinterpret_cast<const ulonglong2*>(g_pk);
#pragma unroll
        for (int i = 0; i < 8; i++) { ulonglong2 v = p[i]; K[2 * i] = v.x; K[2 * i + 1] = v.y; }
    }
    const u64 TWO  = pk2(2.0f, 2.0f);
    const u64 NEG1 = pk2(-1.0f, -1.0f);

    long long tid  = (long long)blockIdx.x * blockDim.x + threadIdx.x;
    long long base = tid * 8;
    if (base >= n) return;

    if (base + 8 <= n) {
        float4 a = *reinterpret_cast<const float4*>(xin + base);
        float4 b = *reinterpret_cast<const float4*>(xin + base + 4);

        u64 r01 = qsvt_pair(a.x, a.y, K, TWO, NEG1);
        u64 r23 = qsvt_pair(a.z, a.w, K, TWO, NEG1);
        u64 r45 = qsvt_pair(b.x, b.y, K, TWO, NEG1);
        u64 r67 = qsvt_pair(b.z, b.w, K, TWO, NEG1);

        float4 o1, o2;
        unpk2(r01, o1.x, o1.y);
        unpk2(r23, o1.z, o1.w);
        unpk2(r45, o2.x, o2.y);
        unpk2(r67, o2.z, o2.w);
        *reinterpret_cast<float4*>(out + base)     = o1;
        *reinterpret_cast<float4*>(out + base + 4) = o2;
    } else {
        for (long long i = base; i < n; i++) {
            u64 r = qsvt_pair(xin[i], 0.0f, K, TWO, NEG1);
            float lo, hi;
            unpk2(r, lo, hi);
            out[i] = lo;
        }
    }
}

extern "C" void kernel_launch(void* const* d_in, const int* in_sizes, int n_in,
                              void* d_out, int out_size) {
    const float* x   = (const float*)d_in[0];
    // d_in[1] = theta: dead (diagonal phase, does not affect <Z>)
    const float* phi = (const float*)d_in[2];
    float* out = (float*)d_out;

    qsvt_setup<<<1, 32>>>(phi);

    int n = out_size;
    long long threads = ((long long)n + 7) / 8;
    int blocks = (int)((threads + 255) / 256);
    qsvt_main<<<blocks, 256>>>(x, out, n);
}